// round 16
// baseline (speedup 1.0000x reference)
#include <cuda_runtime.h>
#include <cuda_fp16.h>
#include <math.h>
#include <stdint.h>

#define BB 8
#define HWN 4096

// -------- scratch (allocation-free rule: __device__ globals) --------
__device__ __half g_Qh[BB*HWN*64];   // [b][p][ci]
__device__ __half g_Kh[BB*HWN*64];   // [b][p][ci]  (word-interleaved groups)
__device__ __half g_Vh[BB*64*HWN];   // [b][ci][p]  (transposed, word-interleaved)
__device__ float g_SW[BB*128*HWN];   // sigmoid gates [b][ci][p] (ci 32..127 used)
// split-KV partials: 2048 units = (b, tile, eighth)
__device__ float  g_Pm[2048*128];
__device__ float  g_Pl[2048*128];
__device__ __half g_PO16[(size_t)2048*128*64];   // unnormalized O partials (f16)

__device__ __forceinline__ uint32_t pack_f16x2(float lo, float hi) {
  uint32_t r;
  asm("cvt.rn.f16x2.f32 %0, %1, %2;" : "=r"(r) : "f"(hi), "f"(lo));
  return r;
}
// interleave word index within each 8-word group: [w0 w4 w1 w5 w2 w6 w3 w7]
__device__ __forceinline__ int ilv(int c) {
  return (c & 24) | (((c & 3) << 1) | ((c >> 2) & 1));
}

// f16 inputs, f32 accumulate
__device__ __forceinline__ void mma_f32acc(float d[4], const uint32_t a[4],
                                           uint32_t b0, uint32_t b1) {
  asm volatile("mma.sync.aligned.m16n8k16.row.col.f32.f16.f16.f32 "
               "{%0,%1,%2,%3}, {%4,%5,%6,%7}, {%8,%9}, {%0,%1,%2,%3};"
               : "+f"(d[0]), "+f"(d[1]), "+f"(d[2]), "+f"(d[3])
               : "r"(a[0]), "r"(a[1]), "r"(a[2]), "r"(a[3]), "r"(b0), "r"(b1));
}
// f16 inputs, f16 accumulate
__device__ __forceinline__ void mma_f16acc(uint32_t d[2], const uint32_t a[4],
                                           uint32_t b0, uint32_t b1) {
  asm volatile("mma.sync.aligned.m16n8k16.row.col.f16.f16.f16.f16 "
               "{%0,%1}, {%2,%3,%4,%5}, {%6,%7}, {%0,%1};"
               : "+r"(d[0]), "+r"(d[1])
               : "r"(a[0]), "r"(a[1]), "r"(a[2]), "r"(a[3]), "r"(b0), "r"(b1));
}

// ===================================================================
// Kernel 1: fused gf-build (upsample+concat) + QKV 1x1 convs (tensor)
// grid (64 rows, B), 384 threads; outs overlays gfs/gf16 -> 2 CTA/SM
// ===================================================================
#define QO_GFS   0
#define QO_GF16  8704
#define QO_OUTS  0
#define QO_W16   13056
#define QO_BIAS  26112
#define QKV_FLOATS 26304

__global__ void __launch_bounds__(384, 2) qkv_kernel(
    const float* __restrict__ x1, const float* __restrict__ x2,
    const float* __restrict__ x3, const float* __restrict__ x4,
    const float* __restrict__ qw, const float* __restrict__ qb,
    const float* __restrict__ kw, const float* __restrict__ kb,
    const float* __restrict__ vw, const float* __restrict__ vb) {
  extern __shared__ float sh[];
  float*    gfs  = sh + QO_GFS;
  uint32_t* gf16 = (uint32_t*)(sh + QO_GF16);
  uint32_t* W16  = (uint32_t*)(sh + QO_W16);
  float*    bias = sh + QO_BIAS;
  float*    outs = sh + QO_OUTS;
  const int b = blockIdx.y, y = blockIdx.x, tid = threadIdx.x;

  for (int i = tid; i < 192*64; i += 384) {
    int r = i >> 6, wd = i & 63;
    const float* src = (r < 64) ? (qw + r*128) : (r < 128 ? kw + (r-64)*128 : vw + (r-128)*128);
    W16[r*68 + wd] = pack_f16x2(src[2*wd], src[2*wd+1]);
  }
  for (int i = tid; i < 192; i += 384)
    bias[i] = (i < 64) ? qb[i] : (i < 128 ? kb[i-64] : vb[i-128]);

  for (int i = tid; i < 32*64; i += 384) {
    int c = i >> 6, x = i & 63;
    gfs[c*68 + x] = x1[((b*32 + c)*64 + y)*64 + x];
  }
  const float* srcs[3] = {x2, x3, x4};
  const int    Hs[3]   = {32, 16, 8};
  #pragma unroll
  for (int lvl = 0; lvl < 3; lvl++) {
    const int H = Hs[lvl];
    const float* src = srcs[lvl];
    float fy = (float)y * (float)(H-1) / 63.0f;
    int y0 = (int)fy; if (y0 > H-1) y0 = H-1;
    int y1i = min(y0+1, H-1);
    float wy = fy - (float)y0;
    for (int i = tid; i < 32*64; i += 384) {
      int c = i >> 6, x = i & 63;
      float fx = (float)x * (float)(H-1) / 63.0f;
      int x0 = (int)fx; if (x0 > H-1) x0 = H-1;
      int x1i = min(x0+1, H-1);
      float wx = fx - (float)x0;
      const float* r0 = src + ((b*32 + c)*H + y0)*H;
      const float* r1 = src + ((b*32 + c)*H + y1i)*H;
      float top = r0[x0]*(1.f-wx) + r0[x1i]*wx;
      float bot = r1[x0]*(1.f-wx) + r1[x1i]*wx;
      gfs[(32*(lvl+1) + c)*68 + x] = top*(1.f-wy) + bot*wy;
    }
  }
  __syncthreads();

  for (int i = tid; i < 64*64; i += 384) {
    int x = i >> 6, cw = i & 63;
    gf16[x*68 + cw] = pack_f16x2(gfs[(2*cw)*68 + x], gfs[(2*cw+1)*68 + x]);
  }
  __syncthreads();

  const int w = tid >> 5, lane = tid & 31;
  const int g = lane >> 2, t = lane & 3;
  float acc[8][4];
  {
    uint32_t qa[8][4];
    #pragma unroll
    for (int kt = 0; kt < 8; kt++) {
      qa[kt][0] = W16[(16*w + g    )*68 + kt*8 + t];
      qa[kt][1] = W16[(16*w + g + 8)*68 + kt*8 + t];
      qa[kt][2] = W16[(16*w + g    )*68 + kt*8 + t + 4];
      qa[kt][3] = W16[(16*w + g + 8)*68 + kt*8 + t + 4];
    }
    #pragma unroll
    for (int nt = 0; nt < 8; nt++) { acc[nt][0]=acc[nt][1]=acc[nt][2]=acc[nt][3]=0.f; }
    #pragma unroll
    for (int kt = 0; kt < 8; kt++) {
      #pragma unroll
      for (int nt = 0; nt < 8; nt++) {
        uint32_t b0 = gf16[(8*nt + g)*68 + kt*8 + t];
        uint32_t b1 = gf16[(8*nt + g)*68 + kt*8 + t + 4];
        mma_f32acc(acc[nt], qa[kt], b0, b1);
      }
    }
  }
  __syncthreads();
  {
    float bv0 = bias[16*w + g], bv1 = bias[16*w + g + 8];
    #pragma unroll
    for (int nt = 0; nt < 8; nt++) {
      *(float2*)&outs[(16*w + g    )*66 + 8*nt + 2*t] = make_float2(acc[nt][0]+bv0, acc[nt][1]+bv0);
      *(float2*)&outs[(16*w + g + 8)*66 + 8*nt + 2*t] = make_float2(acc[nt][2]+bv1, acc[nt][3]+bv1);
    }
  }
  __syncthreads();

  const int pbase = b*HWN + y*64;
  uint32_t* Qu = (uint32_t*)g_Qh + (size_t)pbase*32;
  uint32_t* Ku = (uint32_t*)g_Kh + (size_t)pbase*32;
  for (int i = tid; i < 2048; i += 384) {
    int p = i >> 5, c2 = i & 31;
    Qu[p*32 + c2]      = pack_f16x2(outs[(2*c2)*66 + p],    outs[(2*c2+1)*66 + p]);
    Ku[p*32 + ilv(c2)] = pack_f16x2(outs[(64+2*c2)*66 + p], outs[(65+2*c2)*66 + p]);
  }
  uint32_t* Vu = (uint32_t*)g_Vh;
  for (int i = tid; i < 2048; i += 384) {
    int d = i >> 5, px = i & 31;
    const float* vr = &outs[(128+d)*66];
    Vu[((size_t)(b*64+d)*HWN + y*64)/2 + ilv(px)] = pack_f16x2(vr[2*px], vr[2*px+1]);
  }
}

// ===================================================================
// Kernel 2: f16 tensor flash attention, split-KV eighths, f16 partials
// grid (256 = 32 tiles x 8 eighths, B), 256 threads, 2 CTA/SM
// ===================================================================
#define KVW 40
#define KBYTES (64*KVW*4)
#define STAGE_BYTES (2*KBYTES)

__device__ __forceinline__ void cp_async16(uint32_t smem_dst, const void* gsrc) {
  asm volatile("cp.async.ca.shared.global [%0], [%1], 16;\n"
               :: "r"(smem_dst), "l"(gsrc));
}

__device__ __forceinline__ void prefetch_kv(uint32_t sbase, int b, int jt, int stage, int tid) {
  uint32_t st = sbase + (uint32_t)stage * STAGE_BYTES;
  const __half* Ksrc = g_Kh + ((size_t)b*HWN + jt*64)*64;
  const __half* Vsrc = g_Vh + (size_t)b*64*HWN + jt*64;
  #pragma unroll
  for (int k = 0; k < 4; k++) {
    int i = tid + k*256;
    if (i < 512) {
      int r = i >> 3, c = i & 7;
      cp_async16(st + (uint32_t)(r*KVW*4 + c*16), Ksrc + r*64 + c*8);
    } else {
      int j = i - 512, r = j >> 3, c = j & 7;
      cp_async16(st + KBYTES + (uint32_t)(r*KVW*4 + c*16), Vsrc + (size_t)r*HWN + c*8);
    }
  }
}

__global__ void __launch_bounds__(256, 2) attn_kernel() {
  extern __shared__ float sh[];
  uint32_t sbase = (uint32_t)__cvta_generic_to_shared(sh);
  const int b = blockIdx.y;
  const int u = b*256 + blockIdx.x;           // partial-unit index
  const int m0 = (blockIdx.x >> 3)*128;
  const int jbase = (blockIdx.x & 7)*8;
  const int tid = threadIdx.x, w = tid >> 5, lane = tid & 31;
  const int g = lane >> 2, t = lane & 3;

  const uint32_t* Qu = (const uint32_t*)g_Qh + ((size_t)b*HWN + m0 + w*16)*32;
  uint32_t qa[4][4];
  #pragma unroll
  for (int kt = 0; kt < 4; kt++) {
    qa[kt][0] = Qu[ g   *32 + kt*8 + t    ];
    qa[kt][1] = Qu[(g+8)*32 + kt*8 + t    ];
    qa[kt][2] = Qu[ g   *32 + kt*8 + t + 4];
    qa[kt][3] = Qu[(g+8)*32 + kt*8 + t + 4];
  }

  float m0r = -1e30f, m1r = -1e30f, l0 = 0.f, l1 = 0.f;
  float o[8][4] = {};
  const __half2 l2e2 = __float2half2_rn(1.44269504f);

  prefetch_kv(sbase, b, jbase, 0, tid);
  asm volatile("cp.async.commit_group;\n" ::: "memory");

  for (int jt = 0; jt < 8; jt++) {
    asm volatile("cp.async.wait_group 0;\n" ::: "memory");
    __syncthreads();
    if (jt + 1 < 8) {
      prefetch_kv(sbase, b, jbase + jt + 1, (jt+1)&1, tid);
      asm volatile("cp.async.commit_group;\n" ::: "memory");
    }

    const uint32_t* Ku32 = (const uint32_t*)sh + (jt&1)*(STAGE_BYTES/4);
    const uint32_t* Vu32 = Ku32 + KBYTES/4;

    uint32_t sd[8][2];
    #pragma unroll
    for (int nt = 0; nt < 8; nt++) { sd[nt][0] = 0u; sd[nt][1] = 0u; }
    #pragma unroll
    for (int kt = 0; kt < 4; kt++) {
      #pragma unroll
      for (int nt = 0; nt < 8; nt++) {
        uint2 kb = *(const uint2*)&Ku32[(nt*8 + g)*KVW + kt*8 + 2*t];
        mma_f16acc(sd[nt], qa[kt], kb.x, kb.y);
      }
    }

    __half2 hm0 = *(__half2*)&sd[0][0];
    __half2 hm1 = *(__half2*)&sd[0][1];
    #pragma unroll
    for (int nt = 1; nt < 8; nt++) {
      hm0 = __hmax2(hm0, *(__half2*)&sd[nt][0]);
      hm1 = __hmax2(hm1, *(__half2*)&sd[nt][1]);
    }
    float rmax0 = fmaxf(__low2float(hm0), __high2float(hm0));
    float rmax1 = fmaxf(__low2float(hm1), __high2float(hm1));
    rmax0 = fmaxf(rmax0, __shfl_xor_sync(0xffffffffu, rmax0, 1));
    rmax0 = fmaxf(rmax0, __shfl_xor_sync(0xffffffffu, rmax0, 2));
    rmax1 = fmaxf(rmax1, __shfl_xor_sync(0xffffffffu, rmax1, 1));
    rmax1 = fmaxf(rmax1, __shfl_xor_sync(0xffffffffu, rmax1, 2));
    float mn0 = fmaxf(m0r, rmax0), mn1 = fmaxf(m1r, rmax1);
    float c0 = __expf(m0r - mn0), c1 = __expf(m1r - mn1);
    m0r = mn0; m1r = mn1;

    __half2 off0 = __float2half2_rn(-mn0 * 1.44269504f);
    __half2 off1 = __float2half2_rn(-mn1 * 1.44269504f);
    uint32_t pe[8][2];
    #pragma unroll
    for (int nt = 0; nt < 8; nt++) {
      __half2 x0 = __hfma2(*(__half2*)&sd[nt][0], l2e2, off0);
      __half2 x1 = __hfma2(*(__half2*)&sd[nt][1], l2e2, off1);
      asm("ex2.approx.f16x2 %0, %1;" : "=r"(pe[nt][0]) : "r"(*(uint32_t*)&x0));
      asm("ex2.approx.f16x2 %0, %1;" : "=r"(pe[nt][1]) : "r"(*(uint32_t*)&x1));
    }
    __half2 sum0 = *(__half2*)&pe[0][0];
    __half2 sum1 = *(__half2*)&pe[0][1];
    #pragma unroll
    for (int nt = 1; nt < 8; nt++) {
      sum0 = __hadd2(sum0, *(__half2*)&pe[nt][0]);
      sum1 = __hadd2(sum1, *(__half2*)&pe[nt][1]);
    }
    float2 f0 = __half22float2(sum0), f1 = __half22float2(sum1);
    float rs0 = f0.x + f0.y, rs1 = f1.x + f1.y;
    rs0 += __shfl_xor_sync(0xffffffffu, rs0, 1);
    rs0 += __shfl_xor_sync(0xffffffffu, rs0, 2);
    rs1 += __shfl_xor_sync(0xffffffffu, rs1, 1);
    rs1 += __shfl_xor_sync(0xffffffffu, rs1, 2);
    l0 = l0*c0 + rs0;  l1 = l1*c1 + rs1;
    #pragma unroll
    for (int nt = 0; nt < 8; nt++) {
      o[nt][0] *= c0; o[nt][1] *= c0; o[nt][2] *= c1; o[nt][3] *= c1;
    }

    #pragma unroll
    for (int kt = 0; kt < 4; kt++) {
      uint32_t pa[4] = { pe[2*kt][0], pe[2*kt][1], pe[2*kt+1][0], pe[2*kt+1][1] };
      #pragma unroll
      for (int nt = 0; nt < 8; nt++) {
        uint2 vb2 = *(const uint2*)&Vu32[(nt*8 + g)*KVW + kt*8 + 2*t];
        mma_f32acc(o[nt], pa, vb2.x, vb2.y);
      }
    }
  }

  if (t == 0) {
    g_Pm[(size_t)u*128 + w*16 + g    ] = m0r;
    g_Pm[(size_t)u*128 + w*16 + g + 8] = m1r;
    g_Pl[(size_t)u*128 + w*16 + g    ] = l0;
    g_Pl[(size_t)u*128 + w*16 + g + 8] = l1;
  }
  uint32_t* PO = (uint32_t*)g_PO16 + ((size_t)u*128 + w*16)*32;
  #pragma unroll
  for (int nt = 0; nt < 8; nt++) {
    PO[ g   *32 + nt*4 + t] = pack_f16x2(o[nt][0], o[nt][1]);
    PO[(g+8)*32 + nt*4 + t] = pack_f16x2(o[nt][2], o[nt][3]);
  }
}

// ===================================================================
// Kernel 3: fused 8-way split-KV merge + out-proj + gate MLP + sigmoid + x1 gating
// grid (16 pos-tiles of 256, B), 512 threads (16 warps x 16 rows), 1 CTA/SM
// ===================================================================
#define PJ_AO    0                      // u32 [256][36] = 9216
#define PJ_OW    9216                   // u32 [128][36] = 4608 (ends 13824)
#define PJ_G1W   13824                  // u32 [32][68]  = 2176 (ends 16000)
#define PJ_GF2T  16000                  // u32 [256][36] = 9216 (ends 25216)
#define PJ_SW    0                      // overlay f32 [128][260] = 33280
#define PJ_G2W   33280                  // u32 [128][20] = 2560 (ends 35840)
#define PJ_HT    35840                  // u32 [256][20] = 5120 (ends 40960)
#define PJ_OBS   40960                  // f32 [128]
#define PJ_G1BS  41088                  // f32 [32]
#define PJ_G2BS  41120                  // f32 [128]
#define PJ_WQ    41248                  // f32 [256][8]  (merge weights * inv)
#define PROJ_FLOATS 43296               // 173184 B

__global__ void __launch_bounds__(512, 1) proj_kernel(
    const float* __restrict__ ow_, const float* __restrict__ ob,
    const float* __restrict__ g1w, const float* __restrict__ g1b,
    const float* __restrict__ g2w, const float* __restrict__ g2b,
    const float* __restrict__ x1, float* __restrict__ out) {
  extern __shared__ float sh[];
  uint32_t* ao    = (uint32_t*)(sh + PJ_AO);
  uint32_t* ow36  = (uint32_t*)(sh + PJ_OW);
  uint32_t* g1w68 = (uint32_t*)(sh + PJ_G1W);
  uint32_t* gf2T  = (uint32_t*)(sh + PJ_GF2T);
  float*    sw    = sh + PJ_SW;
  uint32_t* g2w20 = (uint32_t*)(sh + PJ_G2W);
  uint32_t* hT    = (uint32_t*)(sh + PJ_HT);
  float*    obs   = sh + PJ_OBS;
  float*    g1bs  = sh + PJ_G1BS;
  float*    g2bs  = sh + PJ_G2BS;
  float*    wqs   = sh + PJ_WQ;

  const int b = blockIdx.y, p0 = blockIdx.x*256, tid = threadIdx.x;
  const int w = tid >> 5, lane = tid & 31;
  const int g = lane >> 2, t = lane & 3;

  // ---- merge weights: per-row lse combine of the 8 eighths ----
  if (tid < 256) {
    int T2 = 2*blockIdx.x + (tid >> 7), rl = tid & 127;
    int ub2 = b*256 + T2*8;
    float m[8], l[8];
    #pragma unroll
    for (int q = 0; q < 8; q++) {
      m[q] = g_Pm[(size_t)(ub2+q)*128 + rl];
      l[q] = g_Pl[(size_t)(ub2+q)*128 + rl];
    }
    float mx = m[0];
    #pragma unroll
    for (int q = 1; q < 8; q++) mx = fmaxf(mx, m[q]);
    float wq[8], lsum = 0.f;
    #pragma unroll
    for (int q = 0; q < 8; q++) { wq[q] = __expf(m[q] - mx); lsum += wq[q]*l[q]; }
    float inv = 1.f / lsum;
    #pragma unroll
    for (int q = 0; q < 8; q++) wqs[tid*8 + q] = wq[q]*inv;
  }
  // ---- stage weights while wq computes ----
  for (int i = tid; i < 4096; i += 512) {           // ow_ [128][64] -> f16
    int r = i >> 5, wd = i & 31;
    ow36[r*36 + wd] = pack_f16x2(ow_[r*64 + 2*wd], ow_[r*64 + 2*wd + 1]);
  }
  for (int i = tid; i < 2048; i += 512) {           // g1w [32][128] -> f16
    int r = i >> 6, wd = i & 63;
    g1w68[r*68 + wd] = pack_f16x2(g1w[r*128 + 2*wd], g1w[r*128 + 2*wd + 1]);
  }
  for (int i = tid; i < 2048; i += 512) {           // g2w [128][32] -> f16
    int r = i >> 4, wd = i & 15;
    g2w20[r*20 + wd] = pack_f16x2(g2w[r*32 + 2*wd], g2w[r*32 + 2*wd + 1]);
  }
  if (tid < 128) obs[tid]  = ob[tid];
  if (tid >= 128 && tid < 160) g1bs[tid-128] = g1b[tid-128];
  if (tid >= 160 && tid < 288) g2bs[tid-160] = g2b[tid-160];
  __syncthreads();

  // ---- fused merge + AO staging (f16 partials -> f16 ao tile) ----
  {
    const __half2* PO2 = (const __half2*)g_PO16;
    for (int i = tid; i < 8192; i += 512) {
      int r = i >> 5, wd = i & 31;
      int T2 = 2*blockIdx.x + (r >> 7), rl = r & 127;
      size_t base = ((size_t)(b*256 + T2*8)*128 + rl)*32 + wd;
      float ax = 0.f, ay = 0.f;
      #pragma unroll
      for (int q = 0; q < 8; q++) {
        float2 v = __half22float2(PO2[base + (size_t)q*4096]);
        float wv = wqs[r*8 + q];
        ax += wv*v.x; ay += wv*v.y;
      }
      ao[r*36 + wd] = pack_f16x2(ax, ay);
    }
  }
  __syncthreads();

  // ---- GEMM1 (f32 acc): gf2T[pos][o] = AO[pos][d] * ow[o][d]^T + ob ----
  {
    uint32_t qa[4][4];
    #pragma unroll
    for (int kt = 0; kt < 4; kt++) {
      qa[kt][0] = ao[(16*w + g    )*36 + kt*8 + t];
      qa[kt][1] = ao[(16*w + g + 8)*36 + kt*8 + t];
      qa[kt][2] = ao[(16*w + g    )*36 + kt*8 + t + 4];
      qa[kt][3] = ao[(16*w + g + 8)*36 + kt*8 + t + 4];
    }
    #pragma unroll
    for (int half = 0; half < 2; half++) {
      float acc[8][4];
      #pragma unroll
      for (int nt = 0; nt < 8; nt++) { acc[nt][0]=acc[nt][1]=acc[nt][2]=acc[nt][3]=0.f; }
      #pragma unroll
      for (int kt = 0; kt < 4; kt++) {
        #pragma unroll
        for (int nt = 0; nt < 8; nt++) {
          int ntg = half*8 + nt;
          uint32_t b0 = ow36[(ntg*8 + g)*36 + kt*8 + t];
          uint32_t b1 = ow36[(ntg*8 + g)*36 + kt*8 + t + 4];
          mma_f32acc(acc[nt], qa[kt], b0, b1);
        }
      }
      #pragma unroll
      for (int nt = 0; nt < 8; nt++) {
        int ntg = half*8 + nt;
        float b0v = obs[ntg*8 + 2*t], b1v = obs[ntg*8 + 2*t + 1];
        gf2T[(16*w + g    )*36 + ntg*4 + t] = pack_f16x2(acc[nt][0]+b0v, acc[nt][1]+b1v);
        gf2T[(16*w + g + 8)*36 + ntg*4 + t] = pack_f16x2(acc[nt][2]+b0v, acc[nt][3]+b1v);
      }
    }
  }
  __syncwarp();

  // ---- GEMM2 (f32 acc): hT[pos][co] = relu(gf2T * g1w^T + g1b) ----
  uint32_t qa3[2][4];
  {
    uint32_t qa2[8][4];
    #pragma unroll
    for (int kt = 0; kt < 8; kt++) {
      qa2[kt][0] = gf2T[(16*w + g    )*36 + kt*8 + t];
      qa2[kt][1] = gf2T[(16*w + g + 8)*36 + kt*8 + t];
      qa2[kt][2] = gf2T[(16*w + g    )*36 + kt*8 + t + 4];
      qa2[kt][3] = gf2T[(16*w + g + 8)*36 + kt*8 + t + 4];
    }
    float acc2[4][4];
    #pragma unroll
    for (int nt = 0; nt < 4; nt++) { acc2[nt][0]=acc2[nt][1]=acc2[nt][2]=acc2[nt][3]=0.f; }
    #pragma unroll
    for (int kt = 0; kt < 8; kt++) {
      #pragma unroll
      for (int nt = 0; nt < 4; nt++) {
        uint32_t b0 = g1w68[(nt*8 + g)*68 + kt*8 + t];
        uint32_t b1 = g1w68[(nt*8 + g)*68 + kt*8 + t + 4];
        mma_f32acc(acc2[nt], qa2[kt], b0, b1);
      }
    }
    #pragma unroll
    for (int nt = 0; nt < 4; nt++) {
      float b0v = g1bs[nt*8 + 2*t], b1v = g1bs[nt*8 + 2*t + 1];
      float v00 = fmaxf(acc2[nt][0] + b0v, 0.f), v01 = fmaxf(acc2[nt][1] + b1v, 0.f);
      float v10 = fmaxf(acc2[nt][2] + b0v, 0.f), v11 = fmaxf(acc2[nt][3] + b1v, 0.f);
      hT[(16*w + g    )*20 + nt*4 + t] = pack_f16x2(v00, v01);
      hT[(16*w + g + 8)*20 + nt*4 + t] = pack_f16x2(v10, v11);
    }
    __syncwarp();
    #pragma unroll
    for (int kt = 0; kt < 2; kt++) {
      qa3[kt][0] = hT[(16*w + g    )*20 + kt*8 + t];
      qa3[kt][1] = hT[(16*w + g + 8)*20 + kt*8 + t];
      qa3[kt][2] = hT[(16*w + g    )*20 + kt*8 + t + 4];
      qa3[kt][3] = hT[(16*w + g + 8)*20 + kt*8 + t + 4];
    }
  }
  __syncthreads();   // everyone done with ao/ow/g1w/gf2T before sw overlay

  // ---- GEMM3 (f32 acc): sw[ci][pos] = sigmoid(hT * g2w^T + g2b) ----
  #pragma unroll
  for (int half = 0; half < 2; half++) {
    float acc[8][4];
    #pragma unroll
    for (int nt = 0; nt < 8; nt++) { acc[nt][0]=acc[nt][1]=acc[nt][2]=acc[nt][3]=0.f; }
    #pragma unroll
    for (int kt = 0; kt < 2; kt++) {
      #pragma unroll
      for (int nt = 0; nt < 8; nt++) {
        int ntg = half*8 + nt;
        uint32_t b0 = g2w20[(ntg*8 + g)*20 + kt*8 + t];
        uint32_t b1 = g2w20[(ntg*8 + g)*20 + kt*8 + t + 4];
        mma_f32acc(acc[nt], qa3[kt], b0, b1);
      }
    }
    #pragma unroll
    for (int nt = 0; nt < 8; nt++) {
      int ci0 = (half*8 + nt)*8 + 2*t, ci1 = ci0 + 1;
      sw[ci0*260 + 16*w + g    ] = 1.f/(1.f + __expf(-(acc[nt][0] + g2bs[ci0])));
      sw[ci1*260 + 16*w + g    ] = 1.f/(1.f + __expf(-(acc[nt][1] + g2bs[ci1])));
      sw[ci0*260 + 16*w + g + 8] = 1.f/(1.f + __expf(-(acc[nt][2] + g2bs[ci0])));
      sw[ci1*260 + 16*w + g + 8] = 1.f/(1.f + __expf(-(acc[nt][3] + g2bs[ci1])));
    }
  }
  __syncthreads();

  // ---- fused x1 gating: out1 = x1 * (1 + sw[0:32]) ----
  for (int i = tid; i < 2048; i += 512) {
    int ci = i >> 6, pq = i & 63;
    size_t gidx = ((size_t)(b*32 + ci))*HWN + p0 + 4*pq;
    float4 xv = *(const float4*)&x1[gidx];
    float4 sv = *(float4*)&sw[ci*260 + 4*pq];
    float4 ov = make_float4(xv.x*(1.f+sv.x), xv.y*(1.f+sv.y),
                            xv.z*(1.f+sv.z), xv.w*(1.f+sv.w));
    *(float4*)&out[gidx] = ov;
  }
  // ---- store resample channels 32..127 to g_SW ----
  for (int i = tid; i < 6144; i += 512) {
    int ci = 32 + (i >> 6), pq = i & 63;
    float4 v = *(float4*)&sw[ci*260 + 4*pq];
    *(float4*)&g_SW[((size_t)b*128 + ci)*HWN + p0 + 4*pq] = v;
  }
}

// ===================================================================
// Kernel 4: resample gating for x2/x3/x4 only (x1 fused into proj)
// ===================================================================
__device__ __forceinline__ float sample_sw(const float* __restrict__ plane, int y, int x, int OH) {
  float fy = (float)y * 63.0f / (float)(OH-1);
  float fx = (float)x * 63.0f / (float)(OH-1);
  int y0 = (int)fy; if (y0 > 63) y0 = 63;
  int x0 = (int)fx; if (x0 > 63) x0 = 63;
  int y1 = min(y0+1, 63), x1 = min(x0+1, 63);
  float wy = fy - (float)y0, wx = fx - (float)x0;
  float a = plane[y0*64+x0], bv = plane[y0*64+x1];
  float c = plane[y1*64+x0], d = plane[y1*64+x1];
  return (a*(1.f-wx)+bv*wx)*(1.f-wy) + (c*(1.f-wx)+d*wx)*wy;
}

__global__ void gate_kernel(const float* __restrict__ x2, const float* __restrict__ x3,
                            const float* __restrict__ x4, float* __restrict__ out) {
  int idx = blockIdx.x*256 + threadIdx.x;
  const int N1 = BB*32*4096, N2 = BB*32*1024, N3 = BB*32*256, N4 = BB*32*64;
  if (idx < N2) {
    int i = idx;
    int b = i >> 15, c = (i >> 10) & 31, y = (i >> 5) & 31, x = i & 31;
    const float* plane = g_SW + ((size_t)b*128 + 32 + c)*HWN;
    out[N1 + idx] = x2[i]*(1.f + sample_sw(plane, y, x, 32));
  } else if (idx < N2+N3) {
    int i = idx - N2;
    int b = i >> 13, c = (i >> 8) & 31, y = (i >> 4) & 15, x = i & 15;
    const float* plane = g_SW + ((size_t)b*128 + 64 + c)*HWN;
    out[N1 + idx] = x3[i]*(1.f + sample_sw(plane, y, x, 16));
  } else if (idx < N2+N3+N4) {
    int i = idx - N2 - N3;
    int b = i >> 11, c = (i >> 6) & 31, y = (i >> 3) & 7, x = i & 7;
    const float* plane = g_SW + ((size_t)b*128 + 96 + c)*HWN;
    out[N1 + idx] = x4[i]*(1.f + sample_sw(plane, y, x, 8));
  }
}

// ===================================================================
extern "C" void kernel_launch(void* const* d_in, const int* in_sizes, int n_in,
                              void* d_out, int out_size) {
  const float* x1  = (const float*)d_in[0];
  const float* x2  = (const float*)d_in[1];
  const float* x3  = (const float*)d_in[2];
  const float* x4  = (const float*)d_in[3];
  const float* qw  = (const float*)d_in[4];
  const float* qb  = (const float*)d_in[5];
  const float* kw  = (const float*)d_in[6];
  const float* kb  = (const float*)d_in[7];
  const float* vw  = (const float*)d_in[8];
  const float* vb  = (const float*)d_in[9];
  const float* ow_ = (const float*)d_in[10];
  const float* ob  = (const float*)d_in[11];
  const float* g1w = (const float*)d_in[12];
  const float* g1b = (const float*)d_in[13];
  const float* g2w = (const float*)d_in[14];
  const float* g2b = (const float*)d_in[15];
  float* out = (float*)d_out;

  const int QKV_SMEM  = QKV_FLOATS * 4;   // 105216 B
  const int ATTN_SMEM = STAGE_BYTES*2;    // 40960 B
  const int PROJ_SMEM = PROJ_FLOATS * 4;  // 173184 B

  cudaFuncSetAttribute(qkv_kernel,  cudaFuncAttributeMaxDynamicSharedMemorySize, QKV_SMEM);
  cudaFuncSetAttribute(attn_kernel, cudaFuncAttributeMaxDynamicSharedMemorySize, ATTN_SMEM);
  cudaFuncSetAttribute(proj_kernel, cudaFuncAttributeMaxDynamicSharedMemorySize, PROJ_SMEM);

  qkv_kernel <<<dim3(64, BB),  384, QKV_SMEM >>>(x1, x2, x3, x4, qw, qb, kw, kb, vw, vb);
  attn_kernel<<<dim3(256, BB), 256, ATTN_SMEM>>>();
  proj_kernel<<<dim3(16, BB),  512, PROJ_SMEM>>>(ow_, ob, g1w, g1b, g2w, g2b, x1, out);

  const int REST = BB*32*(1024 + 256 + 64);  // 344064
  gate_kernel<<<(REST + 255)/256, 256>>>(x2, x3, x4, out);
}

// round 17
// speedup vs baseline: 1.1100x; 1.1100x over previous
#include <cuda_runtime.h>
#include <cuda_fp16.h>
#include <math.h>
#include <stdint.h>

#define BB 8
#define HWN 4096

// -------- scratch (allocation-free rule: __device__ globals) --------
__device__ __half g_Qh[BB*HWN*64];   // [b][p][ci]
__device__ __half g_Kh[BB*HWN*64];   // [b][p][ci]  (word-interleaved groups)
__device__ __half g_Vh[BB*64*HWN];   // [b][ci][p]  (transposed, word-interleaved)
__device__ float g_SW[BB*128*HWN];   // sigmoid gates [b][ci][p] (ci 32..127 used)
// split-KV partials: 1024 units = (b, tile, quarter)
__device__ float  g_Pm[1024*128];
__device__ float  g_Pl[1024*128];
__device__ __half g_PO16[(size_t)1024*128*64];   // unnormalized O partials (f16)

__device__ __forceinline__ uint32_t pack_f16x2(float lo, float hi) {
  uint32_t r;
  asm("cvt.rn.f16x2.f32 %0, %1, %2;" : "=r"(r) : "f"(hi), "f"(lo));
  return r;
}
// interleave word index within each 8-word group: [w0 w4 w1 w5 w2 w6 w3 w7]
__device__ __forceinline__ int ilv(int c) {
  return (c & 24) | (((c & 3) << 1) | ((c >> 2) & 1));
}

// f16 inputs, f32 accumulate
__device__ __forceinline__ void mma_f32acc(float d[4], const uint32_t a[4],
                                           uint32_t b0, uint32_t b1) {
  asm volatile("mma.sync.aligned.m16n8k16.row.col.f32.f16.f16.f32 "
               "{%0,%1,%2,%3}, {%4,%5,%6,%7}, {%8,%9}, {%0,%1,%2,%3};"
               : "+f"(d[0]), "+f"(d[1]), "+f"(d[2]), "+f"(d[3])
               : "r"(a[0]), "r"(a[1]), "r"(a[2]), "r"(a[3]), "r"(b0), "r"(b1));
}
// f16 inputs, f16 accumulate
__device__ __forceinline__ void mma_f16acc(uint32_t d[2], const uint32_t a[4],
                                           uint32_t b0, uint32_t b1) {
  asm volatile("mma.sync.aligned.m16n8k16.row.col.f16.f16.f16.f16 "
               "{%0,%1}, {%2,%3,%4,%5}, {%6,%7}, {%0,%1};"
               : "+r"(d[0]), "+r"(d[1])
               : "r"(a[0]), "r"(a[1]), "r"(a[2]), "r"(a[3]), "r"(b0), "r"(b1));
}

// ===================================================================
// Kernel 1: fused gf-build (upsample+concat) + QKV 1x1 convs (tensor)
// grid (64 rows, B), 384 threads; outs overlays gfs/gf16 -> 2 CTA/SM
// ===================================================================
#define QO_GFS   0
#define QO_GF16  8704
#define QO_OUTS  0
#define QO_W16   13056
#define QO_BIAS  26112
#define QKV_FLOATS 26304

__global__ void __launch_bounds__(384, 2) qkv_kernel(
    const float* __restrict__ x1, const float* __restrict__ x2,
    const float* __restrict__ x3, const float* __restrict__ x4,
    const float* __restrict__ qw, const float* __restrict__ qb,
    const float* __restrict__ kw, const float* __restrict__ kb,
    const float* __restrict__ vw, const float* __restrict__ vb) {
  extern __shared__ float sh[];
  float*    gfs  = sh + QO_GFS;
  uint32_t* gf16 = (uint32_t*)(sh + QO_GF16);
  uint32_t* W16  = (uint32_t*)(sh + QO_W16);
  float*    bias = sh + QO_BIAS;
  float*    outs = sh + QO_OUTS;
  const int b = blockIdx.y, y = blockIdx.x, tid = threadIdx.x;

  for (int i = tid; i < 192*64; i += 384) {
    int r = i >> 6, wd = i & 63;
    const float* src = (r < 64) ? (qw + r*128) : (r < 128 ? kw + (r-64)*128 : vw + (r-128)*128);
    W16[r*68 + wd] = pack_f16x2(src[2*wd], src[2*wd+1]);
  }
  for (int i = tid; i < 192; i += 384)
    bias[i] = (i < 64) ? qb[i] : (i < 128 ? kb[i-64] : vb[i-128]);

  for (int i = tid; i < 32*64; i += 384) {
    int c = i >> 6, x = i & 63;
    gfs[c*68 + x] = x1[((b*32 + c)*64 + y)*64 + x];
  }
  const float* srcs[3] = {x2, x3, x4};
  const int    Hs[3]   = {32, 16, 8};
  #pragma unroll
  for (int lvl = 0; lvl < 3; lvl++) {
    const int H = Hs[lvl];
    const float* src = srcs[lvl];
    float fy = (float)y * (float)(H-1) / 63.0f;
    int y0 = (int)fy; if (y0 > H-1) y0 = H-1;
    int y1i = min(y0+1, H-1);
    float wy = fy - (float)y0;
    for (int i = tid; i < 32*64; i += 384) {
      int c = i >> 6, x = i & 63;
      float fx = (float)x * (float)(H-1) / 63.0f;
      int x0 = (int)fx; if (x0 > H-1) x0 = H-1;
      int x1i = min(x0+1, H-1);
      float wx = fx - (float)x0;
      const float* r0 = src + ((b*32 + c)*H + y0)*H;
      const float* r1 = src + ((b*32 + c)*H + y1i)*H;
      float top = r0[x0]*(1.f-wx) + r0[x1i]*wx;
      float bot = r1[x0]*(1.f-wx) + r1[x1i]*wx;
      gfs[(32*(lvl+1) + c)*68 + x] = top*(1.f-wy) + bot*wy;
    }
  }
  __syncthreads();

  for (int i = tid; i < 64*64; i += 384) {
    int x = i >> 6, cw = i & 63;
    gf16[x*68 + cw] = pack_f16x2(gfs[(2*cw)*68 + x], gfs[(2*cw+1)*68 + x]);
  }
  __syncthreads();

  const int w = tid >> 5, lane = tid & 31;
  const int g = lane >> 2, t = lane & 3;
  float acc[8][4];
  {
    uint32_t qa[8][4];
    #pragma unroll
    for (int kt = 0; kt < 8; kt++) {
      qa[kt][0] = W16[(16*w + g    )*68 + kt*8 + t];
      qa[kt][1] = W16[(16*w + g + 8)*68 + kt*8 + t];
      qa[kt][2] = W16[(16*w + g    )*68 + kt*8 + t + 4];
      qa[kt][3] = W16[(16*w + g + 8)*68 + kt*8 + t + 4];
    }
    #pragma unroll
    for (int nt = 0; nt < 8; nt++) { acc[nt][0]=acc[nt][1]=acc[nt][2]=acc[nt][3]=0.f; }
    #pragma unroll
    for (int kt = 0; kt < 8; kt++) {
      #pragma unroll
      for (int nt = 0; nt < 8; nt++) {
        uint32_t b0 = gf16[(8*nt + g)*68 + kt*8 + t];
        uint32_t b1 = gf16[(8*nt + g)*68 + kt*8 + t + 4];
        mma_f32acc(acc[nt], qa[kt], b0, b1);
      }
    }
  }
  __syncthreads();
  {
    float bv0 = bias[16*w + g], bv1 = bias[16*w + g + 8];
    #pragma unroll
    for (int nt = 0; nt < 8; nt++) {
      *(float2*)&outs[(16*w + g    )*66 + 8*nt + 2*t] = make_float2(acc[nt][0]+bv0, acc[nt][1]+bv0);
      *(float2*)&outs[(16*w + g + 8)*66 + 8*nt + 2*t] = make_float2(acc[nt][2]+bv1, acc[nt][3]+bv1);
    }
  }
  __syncthreads();

  const int pbase = b*HWN + y*64;
  uint32_t* Qu = (uint32_t*)g_Qh + (size_t)pbase*32;
  uint32_t* Ku = (uint32_t*)g_Kh + (size_t)pbase*32;
  for (int i = tid; i < 2048; i += 384) {
    int p = i >> 5, c2 = i & 31;
    Qu[p*32 + c2]      = pack_f16x2(outs[(2*c2)*66 + p],    outs[(2*c2+1)*66 + p]);
    Ku[p*32 + ilv(c2)] = pack_f16x2(outs[(64+2*c2)*66 + p], outs[(65+2*c2)*66 + p]);
  }
  uint32_t* Vu = (uint32_t*)g_Vh;
  for (int i = tid; i < 2048; i += 384) {
    int d = i >> 5, px = i & 31;
    const float* vr = &outs[(128+d)*66];
    Vu[((size_t)(b*64+d)*HWN + y*64)/2 + ilv(px)] = pack_f16x2(vr[2*px], vr[2*px+1]);
  }
}

// ===================================================================
// Kernel 2: f16 tensor flash attention, split-KV quarters, f16 O-acc
// grid (128 = 32 tiles x 4 quarters, B), 256 threads, 3 CTA/SM
// ===================================================================
#define KVW 40
#define KBYTES (64*KVW*4)
#define STAGE_BYTES (2*KBYTES)

__device__ __forceinline__ void cp_async16(uint32_t smem_dst, const void* gsrc) {
  asm volatile("cp.async.ca.shared.global [%0], [%1], 16;\n"
               :: "r"(smem_dst), "l"(gsrc));
}

__device__ __forceinline__ void prefetch_kv(uint32_t sbase, int b, int jt, int stage, int tid) {
  uint32_t st = sbase + (uint32_t)stage * STAGE_BYTES;
  const __half* Ksrc = g_Kh + ((size_t)b*HWN + jt*64)*64;
  const __half* Vsrc = g_Vh + (size_t)b*64*HWN + jt*64;
  #pragma unroll
  for (int k = 0; k < 4; k++) {
    int i = tid + k*256;
    if (i < 512) {
      int r = i >> 3, c = i & 7;
      cp_async16(st + (uint32_t)(r*KVW*4 + c*16), Ksrc + r*64 + c*8);
    } else {
      int j = i - 512, r = j >> 3, c = j & 7;
      cp_async16(st + KBYTES + (uint32_t)(r*KVW*4 + c*16), Vsrc + (size_t)r*HWN + c*8);
    }
  }
}

__global__ void __launch_bounds__(256, 3) attn_kernel() {
  extern __shared__ float sh[];
  uint32_t sbase = (uint32_t)__cvta_generic_to_shared(sh);
  const int b = blockIdx.y;
  const int u = b*128 + blockIdx.x;           // partial-unit index
  const int m0 = (blockIdx.x >> 2)*128;
  const int jbase = (blockIdx.x & 3)*16;
  const int tid = threadIdx.x, w = tid >> 5, lane = tid & 31;
  const int g = lane >> 2, t = lane & 3;

  const uint32_t* Qu = (const uint32_t*)g_Qh + ((size_t)b*HWN + m0 + w*16)*32;
  uint32_t qa[4][4];
  #pragma unroll
  for (int kt = 0; kt < 4; kt++) {
    qa[kt][0] = Qu[ g   *32 + kt*8 + t    ];
    qa[kt][1] = Qu[(g+8)*32 + kt*8 + t    ];
    qa[kt][2] = Qu[ g   *32 + kt*8 + t + 4];
    qa[kt][3] = Qu[(g+8)*32 + kt*8 + t + 4];
  }

  float m0r = -1e30f, m1r = -1e30f, l0 = 0.f, l1 = 0.f;
  uint32_t o[8][2];
  #pragma unroll
  for (int nt = 0; nt < 8; nt++) { o[nt][0] = 0u; o[nt][1] = 0u; }
  const __half2 l2e2 = __float2half2_rn(1.44269504f);

  prefetch_kv(sbase, b, jbase, 0, tid);
  asm volatile("cp.async.commit_group;\n" ::: "memory");

  for (int jt = 0; jt < 16; jt++) {
    asm volatile("cp.async.wait_group 0;\n" ::: "memory");
    __syncthreads();
    if (jt + 1 < 16) {
      prefetch_kv(sbase, b, jbase + jt + 1, (jt+1)&1, tid);
      asm volatile("cp.async.commit_group;\n" ::: "memory");
    }

    const uint32_t* Ku32 = (const uint32_t*)sh + (jt&1)*(STAGE_BYTES/4);
    const uint32_t* Vu32 = Ku32 + KBYTES/4;

    uint32_t sd[8][2];
    #pragma unroll
    for (int nt = 0; nt < 8; nt++) { sd[nt][0] = 0u; sd[nt][1] = 0u; }
    #pragma unroll
    for (int kt = 0; kt < 4; kt++) {
      #pragma unroll
      for (int nt = 0; nt < 8; nt++) {
        uint2 kb = *(const uint2*)&Ku32[(nt*8 + g)*KVW + kt*8 + 2*t];
        mma_f16acc(sd[nt], qa[kt], kb.x, kb.y);
      }
    }

    __half2 hm0 = *(__half2*)&sd[0][0];
    __half2 hm1 = *(__half2*)&sd[0][1];
    #pragma unroll
    for (int nt = 1; nt < 8; nt++) {
      hm0 = __hmax2(hm0, *(__half2*)&sd[nt][0]);
      hm1 = __hmax2(hm1, *(__half2*)&sd[nt][1]);
    }
    float rmax0 = fmaxf(__low2float(hm0), __high2float(hm0));
    float rmax1 = fmaxf(__low2float(hm1), __high2float(hm1));
    rmax0 = fmaxf(rmax0, __shfl_xor_sync(0xffffffffu, rmax0, 1));
    rmax0 = fmaxf(rmax0, __shfl_xor_sync(0xffffffffu, rmax0, 2));
    rmax1 = fmaxf(rmax1, __shfl_xor_sync(0xffffffffu, rmax1, 1));
    rmax1 = fmaxf(rmax1, __shfl_xor_sync(0xffffffffu, rmax1, 2));
    float mn0 = fmaxf(m0r, rmax0), mn1 = fmaxf(m1r, rmax1);
    float c0 = __expf(m0r - mn0), c1 = __expf(m1r - mn1);
    m0r = mn0; m1r = mn1;

    __half2 off0 = __float2half2_rn(-mn0 * 1.44269504f);
    __half2 off1 = __float2half2_rn(-mn1 * 1.44269504f);
    uint32_t pe[8][2];
    #pragma unroll
    for (int nt = 0; nt < 8; nt++) {
      __half2 x0 = __hfma2(*(__half2*)&sd[nt][0], l2e2, off0);
      __half2 x1 = __hfma2(*(__half2*)&sd[nt][1], l2e2, off1);
      asm("ex2.approx.f16x2 %0, %1;" : "=r"(pe[nt][0]) : "r"(*(uint32_t*)&x0));
      asm("ex2.approx.f16x2 %0, %1;" : "=r"(pe[nt][1]) : "r"(*(uint32_t*)&x1));
    }
    __half2 sum0 = *(__half2*)&pe[0][0];
    __half2 sum1 = *(__half2*)&pe[0][1];
    #pragma unroll
    for (int nt = 1; nt < 8; nt++) {
      sum0 = __hadd2(sum0, *(__half2*)&pe[nt][0]);
      sum1 = __hadd2(sum1, *(__half2*)&pe[nt][1]);
    }
    float2 f0 = __half22float2(sum0), f1 = __half22float2(sum1);
    float rs0 = f0.x + f0.y, rs1 = f1.x + f1.y;
    rs0 += __shfl_xor_sync(0xffffffffu, rs0, 1);
    rs0 += __shfl_xor_sync(0xffffffffu, rs0, 2);
    rs1 += __shfl_xor_sync(0xffffffffu, rs1, 1);
    rs1 += __shfl_xor_sync(0xffffffffu, rs1, 2);
    l0 = l0*c0 + rs0;  l1 = l1*c1 + rs1;

    // rescale f16 O accumulator
    __half2 c02 = __float2half2_rn(c0), c12 = __float2half2_rn(c1);
    #pragma unroll
    for (int nt = 0; nt < 8; nt++) {
      __half2 v0 = __hmul2(*(__half2*)&o[nt][0], c02);
      __half2 v1 = __hmul2(*(__half2*)&o[nt][1], c12);
      o[nt][0] = *(uint32_t*)&v0;
      o[nt][1] = *(uint32_t*)&v1;
    }

    #pragma unroll
    for (int kt = 0; kt < 4; kt++) {
      uint32_t pa[4] = { pe[2*kt][0], pe[2*kt][1], pe[2*kt+1][0], pe[2*kt+1][1] };
      #pragma unroll
      for (int nt = 0; nt < 8; nt++) {
        uint2 vb2 = *(const uint2*)&Vu32[(nt*8 + g)*KVW + kt*8 + 2*t];
        mma_f16acc(o[nt], pa, vb2.x, vb2.y);
      }
    }
  }

  if (t == 0) {
    g_Pm[(size_t)u*128 + w*16 + g    ] = m0r;
    g_Pm[(size_t)u*128 + w*16 + g + 8] = m1r;
    g_Pl[(size_t)u*128 + w*16 + g    ] = l0;
    g_Pl[(size_t)u*128 + w*16 + g + 8] = l1;
  }
  // O already packed f16x2 in C-fragment layout -> direct store
  uint32_t* PO = (uint32_t*)g_PO16 + ((size_t)u*128 + w*16)*32;
  #pragma unroll
  for (int nt = 0; nt < 8; nt++) {
    PO[ g   *32 + nt*4 + t] = o[nt][0];
    PO[(g+8)*32 + nt*4 + t] = o[nt][1];
  }
}

// ===================================================================
// Kernel 3: fused 4-way split-KV merge + out-proj + gate MLP + sigmoid + x1 gating
// grid (16 pos-tiles of 256, B), 512 threads (16 warps x 16 rows), 1 CTA/SM
// ===================================================================
#define PJ_AO    0                      // u32 [256][36] = 9216
#define PJ_OW    9216                   // u32 [128][36] = 4608 (ends 13824)
#define PJ_G1W   13824                  // u32 [32][68]  = 2176 (ends 16000)
#define PJ_GF2T  16000                  // u32 [256][36] = 9216 (ends 25216)
#define PJ_SW    0                      // overlay f32 [128][260] = 33280
#define PJ_G2W   33280                  // u32 [128][20] = 2560 (ends 35840)
#define PJ_HT    35840                  // u32 [256][20] = 5120 (ends 40960)
#define PJ_OBS   40960                  // f32 [128]
#define PJ_G1BS  41088                  // f32 [32]
#define PJ_G2BS  41120                  // f32 [128]
#define PJ_WQ    41248                  // f32 [256][4]
#define PROJ_FLOATS 42272               // 169088 B

__global__ void __launch_bounds__(512, 1) proj_kernel(
    const float* __restrict__ ow_, const float* __restrict__ ob,
    const float* __restrict__ g1w, const float* __restrict__ g1b,
    const float* __restrict__ g2w, const float* __restrict__ g2b,
    const float* __restrict__ x1, float* __restrict__ out) {
  extern __shared__ float sh[];
  uint32_t* ao    = (uint32_t*)(sh + PJ_AO);
  uint32_t* ow36  = (uint32_t*)(sh + PJ_OW);
  uint32_t* g1w68 = (uint32_t*)(sh + PJ_G1W);
  uint32_t* gf2T  = (uint32_t*)(sh + PJ_GF2T);
  float*    sw    = sh + PJ_SW;
  uint32_t* g2w20 = (uint32_t*)(sh + PJ_G2W);
  uint32_t* hT    = (uint32_t*)(sh + PJ_HT);
  float*    obs   = sh + PJ_OBS;
  float*    g1bs  = sh + PJ_G1BS;
  float*    g2bs  = sh + PJ_G2BS;
  float*    wqs   = sh + PJ_WQ;

  const int b = blockIdx.y, p0 = blockIdx.x*256, tid = threadIdx.x;
  const int w = tid >> 5, lane = tid & 31;
  const int g = lane >> 2, t = lane & 3;

  // ---- merge weights: per-row lse combine of the 4 quarters ----
  if (tid < 256) {
    int T2 = 2*blockIdx.x + (tid >> 7), rl = tid & 127;
    int ub2 = b*128 + T2*4;
    float m[4], l[4];
    #pragma unroll
    for (int q = 0; q < 4; q++) {
      m[q] = g_Pm[(size_t)(ub2+q)*128 + rl];
      l[q] = g_Pl[(size_t)(ub2+q)*128 + rl];
    }
    float mx = fmaxf(fmaxf(m[0], m[1]), fmaxf(m[2], m[3]));
    float wq[4], lsum = 0.f;
    #pragma unroll
    for (int q = 0; q < 4; q++) { wq[q] = __expf(m[q] - mx); lsum += wq[q]*l[q]; }
    float inv = 1.f / lsum;
    #pragma unroll
    for (int q = 0; q < 4; q++) wqs[tid*4 + q] = wq[q]*inv;
  }
  // ---- stage weights while wq computes ----
  for (int i = tid; i < 4096; i += 512) {           // ow_ [128][64] -> f16
    int r = i >> 5, wd = i & 31;
    ow36[r*36 + wd] = pack_f16x2(ow_[r*64 + 2*wd], ow_[r*64 + 2*wd + 1]);
  }
  for (int i = tid; i < 2048; i += 512) {           // g1w [32][128] -> f16
    int r = i >> 6, wd = i & 63;
    g1w68[r*68 + wd] = pack_f16x2(g1w[r*128 + 2*wd], g1w[r*128 + 2*wd + 1]);
  }
  for (int i = tid; i < 2048; i += 512) {           // g2w [128][32] -> f16
    int r = i >> 4, wd = i & 15;
    g2w20[r*20 + wd] = pack_f16x2(g2w[r*32 + 2*wd], g2w[r*32 + 2*wd + 1]);
  }
  if (tid < 128) obs[tid]  = ob[tid];
  if (tid >= 128 && tid < 160) g1bs[tid-128] = g1b[tid-128];
  if (tid >= 160 && tid < 288) g2bs[tid-160] = g2b[tid-160];
  __syncthreads();

  // ---- fused merge + AO staging (f16 partials -> f16 ao tile) ----
  {
    const __half2* PO2 = (const __half2*)g_PO16;
    for (int i = tid; i < 8192; i += 512) {
      int r = i >> 5, wd = i & 31;
      int T2 = 2*blockIdx.x + (r >> 7), rl = r & 127;
      size_t base = ((size_t)(b*128 + T2*4)*128 + rl)*32 + wd;
      float ax = 0.f, ay = 0.f;
      #pragma unroll
      for (int q = 0; q < 4; q++) {
        float2 v = __half22float2(PO2[base + (size_t)q*4096]);
        float wv = wqs[r*4 + q];
        ax += wv*v.x; ay += wv*v.y;
      }
      ao[r*36 + wd] = pack_f16x2(ax, ay);
    }
  }
  __syncthreads();

  // ---- GEMM1 (f32 acc): gf2T[pos][o] = AO[pos][d] * ow[o][d]^T + ob ----
  {
    uint32_t qa[4][4];
    #pragma unroll
    for (int kt = 0; kt < 4; kt++) {
      qa[kt][0] = ao[(16*w + g    )*36 + kt*8 + t];
      qa[kt][1] = ao[(16*w + g + 8)*36 + kt*8 + t];
      qa[kt][2] = ao[(16*w + g    )*36 + kt*8 + t + 4];
      qa[kt][3] = ao[(16*w + g + 8)*36 + kt*8 + t + 4];
    }
    #pragma unroll
    for (int half = 0; half < 2; half++) {
      float acc[8][4];
      #pragma unroll
      for (int nt = 0; nt < 8; nt++) { acc[nt][0]=acc[nt][1]=acc[nt][2]=acc[nt][3]=0.f; }
      #pragma unroll
      for (int kt = 0; kt < 4; kt++) {
        #pragma unroll
        for (int nt = 0; nt < 8; nt++) {
          int ntg = half*8 + nt;
          uint32_t b0 = ow36[(ntg*8 + g)*36 + kt*8 + t];
          uint32_t b1 = ow36[(ntg*8 + g)*36 + kt*8 + t + 4];
          mma_f32acc(acc[nt], qa[kt], b0, b1);
        }
      }
      #pragma unroll
      for (int nt = 0; nt < 8; nt++) {
        int ntg = half*8 + nt;
        float b0v = obs[ntg*8 + 2*t], b1v = obs[ntg*8 + 2*t + 1];
        gf2T[(16*w + g    )*36 + ntg*4 + t] = pack_f16x2(acc[nt][0]+b0v, acc[nt][1]+b1v);
        gf2T[(16*w + g + 8)*36 + ntg*4 + t] = pack_f16x2(acc[nt][2]+b0v, acc[nt][3]+b1v);
      }
    }
  }
  __syncwarp();

  // ---- GEMM2 (f32 acc): hT[pos][co] = relu(gf2T * g1w^T + g1b) ----
  uint32_t qa3[2][4];
  {
    uint32_t qa2[8][4];
    #pragma unroll
    for (int kt = 0; kt < 8; kt++) {
      qa2[kt][0] = gf2T[(16*w + g    )*36 + kt*8 + t];
      qa2[kt][1] = gf2T[(16*w + g + 8)*36 + kt*8 + t];
      qa2[kt][2] = gf2T[(16*w + g    )*36 + kt*8 + t + 4];
      qa2[kt][3] = gf2T[(16*w + g + 8)*36 + kt*8 + t + 4];
    }
    float acc2[4][4];
    #pragma unroll
    for (int nt = 0; nt < 4; nt++) { acc2[nt][0]=acc2[nt][1]=acc2[nt][2]=acc2[nt][3]=0.f; }
    #pragma unroll
    for (int kt = 0; kt < 8; kt++) {
      #pragma unroll
      for (int nt = 0; nt < 4; nt++) {
        uint32_t b0 = g1w68[(nt*8 + g)*68 + kt*8 + t];
        uint32_t b1 = g1w68[(nt*8 + g)*68 + kt*8 + t + 4];
        mma_f32acc(acc2[nt], qa2[kt], b0, b1);
      }
    }
    #pragma unroll
    for (int nt = 0; nt < 4; nt++) {
      float b0v = g1bs[nt*8 + 2*t], b1v = g1bs[nt*8 + 2*t + 1];
      float v00 = fmaxf(acc2[nt][0] + b0v, 0.f), v01 = fmaxf(acc2[nt][1] + b1v, 0.f);
      float v10 = fmaxf(acc2[nt][2] + b0v, 0.f), v11 = fmaxf(acc2[nt][3] + b1v, 0.f);
      hT[(16*w + g    )*20 + nt*4 + t] = pack_f16x2(v00, v01);
      hT[(16*w + g + 8)*20 + nt*4 + t] = pack_f16x2(v10, v11);
    }
    __syncwarp();
    #pragma unroll
    for (int kt = 0; kt < 2; kt++) {
      qa3[kt][0] = hT[(16*w + g    )*20 + kt*8 + t];
      qa3[kt][1] = hT[(16*w + g + 8)*20 + kt*8 + t];
      qa3[kt][2] = hT[(16*w + g    )*20 + kt*8 + t + 4];
      qa3[kt][3] = hT[(16*w + g + 8)*20 + kt*8 + t + 4];
    }
  }
  __syncthreads();   // everyone done with ao/ow/g1w/gf2T before sw overlay

  // ---- GEMM3 (f32 acc): sw[ci][pos] = sigmoid(hT * g2w^T + g2b) ----
  #pragma unroll
  for (int half = 0; half < 2; half++) {
    float acc[8][4];
    #pragma unroll
    for (int nt = 0; nt < 8; nt++) { acc[nt][0]=acc[nt][1]=acc[nt][2]=acc[nt][3]=0.f; }
    #pragma unroll
    for (int kt = 0; kt < 2; kt++) {
      #pragma unroll
      for (int nt = 0; nt < 8; nt++) {
        int ntg = half*8 + nt;
        uint32_t b0 = g2w20[(ntg*8 + g)*20 + kt*8 + t];
        uint32_t b1 = g2w20[(ntg*8 + g)*20 + kt*8 + t + 4];
        mma_f32acc(acc[nt], qa3[kt], b0, b1);
      }
    }
    #pragma unroll
    for (int nt = 0; nt < 8; nt++) {
      int ci0 = (half*8 + nt)*8 + 2*t, ci1 = ci0 + 1;
      sw[ci0*260 + 16*w + g    ] = 1.f/(1.f + __expf(-(acc[nt][0] + g2bs[ci0])));
      sw[ci1*260 + 16*w + g    ] = 1.f/(1.f + __expf(-(acc[nt][1] + g2bs[ci1])));
      sw[ci0*260 + 16*w + g + 8] = 1.f/(1.f + __expf(-(acc[nt][2] + g2bs[ci0])));
      sw[ci1*260 + 16*w + g + 8] = 1.f/(1.f + __expf(-(acc[nt][3] + g2bs[ci1])));
    }
  }
  __syncthreads();

  // ---- fused x1 gating: out1 = x1 * (1 + sw[0:32]) ----
  for (int i = tid; i < 2048; i += 512) {
    int ci = i >> 6, pq = i & 63;
    size_t gidx = ((size_t)(b*32 + ci))*HWN + p0 + 4*pq;
    float4 xv = *(const float4*)&x1[gidx];
    float4 sv = *(float4*)&sw[ci*260 + 4*pq];
    float4 ov = make_float4(xv.x*(1.f+sv.x), xv.y*(1.f+sv.y),
                            xv.z*(1.f+sv.z), xv.w*(1.f+sv.w));
    *(float4*)&out[gidx] = ov;
  }
  // ---- store resample channels 32..127 to g_SW ----
  for (int i = tid; i < 6144; i += 512) {
    int ci = 32 + (i >> 6), pq = i & 63;
    float4 v = *(float4*)&sw[ci*260 + 4*pq];
    *(float4*)&g_SW[((size_t)b*128 + ci)*HWN + p0 + 4*pq] = v;
  }
}

// ===================================================================
// Kernel 4: resample gating for x2/x3/x4 only (x1 fused into proj)
// ===================================================================
__device__ __forceinline__ float sample_sw(const float* __restrict__ plane, int y, int x, int OH) {
  float fy = (float)y * 63.0f / (float)(OH-1);
  float fx = (float)x * 63.0f / (float)(OH-1);
  int y0 = (int)fy; if (y0 > 63) y0 = 63;
  int x0 = (int)fx; if (x0 > 63) x0 = 63;
  int y1 = min(y0+1, 63), x1 = min(x0+1, 63);
  float wy = fy - (float)y0, wx = fx - (float)x0;
  float a = plane[y0*64+x0], bv = plane[y0*64+x1];
  float c = plane[y1*64+x0], d = plane[y1*64+x1];
  return (a*(1.f-wx)+bv*wx)*(1.f-wy) + (c*(1.f-wx)+d*wx)*wy;
}

__global__ void gate_kernel(const float* __restrict__ x2, const float* __restrict__ x3,
                            const float* __restrict__ x4, float* __restrict__ out) {
  int idx = blockIdx.x*256 + threadIdx.x;
  const int N1 = BB*32*4096, N2 = BB*32*1024, N3 = BB*32*256, N4 = BB*32*64;
  if (idx < N2) {
    int i = idx;
    int b = i >> 15, c = (i >> 10) & 31, y = (i >> 5) & 31, x = i & 31;
    const float* plane = g_SW + ((size_t)b*128 + 32 + c)*HWN;
    out[N1 + idx] = x2[i]*(1.f + sample_sw(plane, y, x, 32));
  } else if (idx < N2+N3) {
    int i = idx - N2;
    int b = i >> 13, c = (i >> 8) & 31, y = (i >> 4) & 15, x = i & 15;
    const float* plane = g_SW + ((size_t)b*128 + 64 + c)*HWN;
    out[N1 + idx] = x3[i]*(1.f + sample_sw(plane, y, x, 16));
  } else if (idx < N2+N3+N4) {
    int i = idx - N2 - N3;
    int b = i >> 11, c = (i >> 6) & 31, y = (i >> 3) & 7, x = i & 7;
    const float* plane = g_SW + ((size_t)b*128 + 96 + c)*HWN;
    out[N1 + idx] = x4[i]*(1.f + sample_sw(plane, y, x, 8));
  }
}

// ===================================================================
extern "C" void kernel_launch(void* const* d_in, const int* in_sizes, int n_in,
                              void* d_out, int out_size) {
  const float* x1  = (const float*)d_in[0];
  const float* x2  = (const float*)d_in[1];
  const float* x3  = (const float*)d_in[2];
  const float* x4  = (const float*)d_in[3];
  const float* qw  = (const float*)d_in[4];
  const float* qb  = (const float*)d_in[5];
  const float* kw  = (const float*)d_in[6];
  const float* kb  = (const float*)d_in[7];
  const float* vw  = (const float*)d_in[8];
  const float* vb  = (const float*)d_in[9];
  const float* ow_ = (const float*)d_in[10];
  const float* ob  = (const float*)d_in[11];
  const float* g1w = (const float*)d_in[12];
  const float* g1b = (const float*)d_in[13];
  const float* g2w = (const float*)d_in[14];
  const float* g2b = (const float*)d_in[15];
  float* out = (float*)d_out;

  const int QKV_SMEM  = QKV_FLOATS * 4;   // 105216 B
  const int ATTN_SMEM = STAGE_BYTES*2;    // 40960 B
  const int PROJ_SMEM = PROJ_FLOATS * 4;  // 169088 B

  cudaFuncSetAttribute(qkv_kernel,  cudaFuncAttributeMaxDynamicSharedMemorySize, QKV_SMEM);
  cudaFuncSetAttribute(attn_kernel, cudaFuncAttributeMaxDynamicSharedMemorySize, ATTN_SMEM);
  cudaFuncSetAttribute(proj_kernel, cudaFuncAttributeMaxDynamicSharedMemorySize, PROJ_SMEM);

  qkv_kernel <<<dim3(64, BB),  384, QKV_SMEM >>>(x1, x2, x3, x4, qw, qb, kw, kb, vw, vb);
  attn_kernel<<<dim3(128, BB), 256, ATTN_SMEM>>>();
  proj_kernel<<<dim3(16, BB),  512, PROJ_SMEM>>>(ow_, ob, g1w, g1b, g2w, g2b, x1, out);

  const int REST = BB*32*(1024 + 256 + 64);  // 344064
  gate_kernel<<<(REST + 255)/256, 256>>>(x2, x3, x4, out);
}